// round 5
// baseline (speedup 1.0000x reference)
#include <cuda_runtime.h>

#define BATCH 16
#define CC    64
#define HID   128
#define EE    4
#define NPIX  16384      // 128*128
#define PX    64         // pixels per subtile
#define TPB   256
#define CHUNKS 32        // chunks per (b,e); 512 px per chunk
#define SUBT   8         // subtiles per chunk

// SMEM float offsets (strides padded to reduce bank conflicts)
#define OFF_W1  0        // [64][132]
#define OFF_W2  8448     // [128][132]
#define OFF_W3  25344    // [128][68]
#define OFF_T1  34048    // [128]
#define OFF_T2  34176    // [128]
#define OFF_B3  34304    // [64]
#define OFF_X   34368    // [64][68]
#define OFF_H1  38720    // [128][68]
#define OFF_H2  47424    // [128][68]
#define SMEM_FLOATS 56128
#define SMEM_BYTES  (SMEM_FLOATS * 4)

__device__ float g_gap[BATCH * CC];
__device__ float g_gated[BATCH * EE];

// ---------------------------------------------------------------------------
// packed f32x2 helpers (FFMA2: 2x fp32 FMA throughput on sm_103a)
// ---------------------------------------------------------------------------
__device__ __forceinline__ unsigned long long pk2(float a, float b) {
    unsigned long long r;
    asm("mov.b64 %0, {%1, %2};" : "=l"(r) : "f"(a), "f"(b));
    return r;
}
__device__ __forceinline__ void ffma2(unsigned long long& d,
                                      unsigned long long a,
                                      unsigned long long b) {
    asm("fma.rn.f32x2 %0, %1, %2, %0;" : "+l"(d) : "l"(a), "l"(b));
}
__device__ __forceinline__ float2 up2(unsigned long long v) {
    float2 f;
    asm("mov.b64 {%0, %1}, %2;" : "=f"(f.x), "=f"(f.y) : "l"(v));
    return f;
}

// ---------------------------------------------------------------------------
// global average pool: one block per (b,c) row of 16384 pixels
// ---------------------------------------------------------------------------
__global__ void gap_kernel(const float* __restrict__ x) {
    const int bc = blockIdx.x;
    const float4* p = (const float4*)(x + (size_t)bc * NPIX);
    float s = 0.f;
    for (int i = threadIdx.x; i < NPIX / 4; i += TPB) {
        float4 v = p[i];
        s += (v.x + v.y) + (v.z + v.w);
    }
    #pragma unroll
    for (int o = 16; o; o >>= 1) s += __shfl_down_sync(0xffffffffu, s, o);
    __shared__ float red[8];
    if ((threadIdx.x & 31) == 0) red[threadIdx.x >> 5] = s;
    __syncthreads();
    if (threadIdx.x == 0) {
        float tot = 0.f;
        #pragma unroll
        for (int i = 0; i < 8; i++) tot += red[i];
        g_gap[bc] = tot * (1.f / NPIX);
    }
}

// ---------------------------------------------------------------------------
// gate: logits -> softmax -> top2 -> normalized gated weights + aux loss
// ---------------------------------------------------------------------------
__global__ void gate_kernel(const float* __restrict__ gw,
                            const float* __restrict__ gb,
                            float* __restrict__ aux_out) {
    __shared__ float logit_s[BATCH][EE];
    __shared__ float gsh[BATCH][EE];
    const int t = threadIdx.x;
    if (t < BATCH * EE) {
        const int b = t >> 2, e = t & 3;
        float s = gb[e];
        const float* gp = g_gap + b * CC;
        #pragma unroll 8
        for (int c = 0; c < CC; c++) s += gp[c] * gw[e * CC + c];
        logit_s[b][e] = s;
    }
    __syncthreads();
    if (t < BATCH) {
        const int b = t;
        float l[EE];
        float mx = -1e30f;
        #pragma unroll
        for (int e = 0; e < EE; e++) { l[e] = logit_s[b][e]; mx = fmaxf(mx, l[e]); }
        float sum = 0.f;
        #pragma unroll
        for (int e = 0; e < EE; e++) { l[e] = expf(l[e] - mx); sum += l[e]; }
        #pragma unroll
        for (int e = 0; e < EE; e++) l[e] /= sum;
        // top-2 (ties -> lower index, matching jax top_k)
        int i1 = 0;
        for (int e = 1; e < EE; e++) if (l[e] > l[i1]) i1 = e;
        int i2 = -1;
        for (int e = 0; e < EE; e++) {
            if (e == i1) continue;
            if (i2 < 0 || l[e] > l[i2]) i2 = e;
        }
        const float denom = l[i1] + l[i2] + 1e-8f;
        #pragma unroll
        for (int e = 0; e < EE; e++) {
            float gv = (e == i1 || e == i2) ? l[e] / denom : 0.f;
            gsh[b][e] = gv;
            g_gated[b * EE + e] = gv;
        }
    }
    __syncthreads();
    if (t == 0) {
        float u[EE];
        float mean = 0.f;
        #pragma unroll
        for (int e = 0; e < EE; e++) {
            float s = 0.f;
            for (int b = 0; b < BATCH; b++) s += gsh[b][e];
            u[e] = s;
            mean += s;
        }
        mean *= (1.f / EE);
        float var = 0.f;
        #pragma unroll
        for (int e = 0; e < EE; e++) { float d = u[e] - mean; var += d * d; }
        var *= (1.f / EE);
        *aux_out = var / (mean * mean + 1e-10f);
    }
}

// ---------------------------------------------------------------------------
// fused 3-layer expert: one CTA per (chunk, expert, batch); skips gated==0
// ---------------------------------------------------------------------------
__global__ __launch_bounds__(TPB, 1)
void moe_main(const float* __restrict__ x,
              const float* __restrict__ W1, const float* __restrict__ b1,
              const float* __restrict__ g1, const float* __restrict__ be1,
              const float* __restrict__ m1, const float* __restrict__ v1,
              const float* __restrict__ W2, const float* __restrict__ b2,
              const float* __restrict__ g2, const float* __restrict__ be2,
              const float* __restrict__ m2, const float* __restrict__ v2,
              const float* __restrict__ W3, const float* __restrict__ b3,
              float* __restrict__ out) {
    extern __shared__ float sm[];
    const int chunk = blockIdx.x;
    const int e     = blockIdx.y;
    const int b     = blockIdx.z;
    const float gval = g_gated[b * EE + e];
    if (gval == 0.f) return;

    float* W1s = sm + OFF_W1;   // [c][132] BN-folded
    float* W2s = sm + OFF_W2;   // [i][132] BN-folded
    float* W3s = sm + OFF_W3;   // [i][68]  gate-folded
    float* t1s = sm + OFF_T1;
    float* t2s = sm + OFF_T2;
    float* b3s = sm + OFF_B3;
    float* Xs  = sm + OFF_X;    // [c][68]
    float* H1s = sm + OFF_H1;   // [o][68]
    float* H2s = sm + OFF_H2;   // [o][68]
    const int t = threadIdx.x;

    // ---- load + fold weights (BN eval-mode fold, gate-weight fold into W3/b3)
    {
        float* s1 = Xs;         // temp scale storage (Xs unused yet)
        float* s2 = Xs + 128;
        for (int o = t; o < HID; o += TPB) {
            float inv1 = g1[e * HID + o] * rsqrtf(v1[e * HID + o] + 1e-5f);
            s1[o] = inv1;
            t1s[o] = (b1[e * HID + o] - m1[e * HID + o]) * inv1 + be1[e * HID + o];
            float inv2 = g2[e * HID + o] * rsqrtf(v2[e * HID + o] + 1e-5f);
            s2[o] = inv2;
            t2s[o] = (b2[e * HID + o] - m2[e * HID + o]) * inv2 + be2[e * HID + o];
        }
        for (int c = t; c < CC; c += TPB) b3s[c] = b3[e * CC + c] * gval;
        __syncthreads();
        for (int idx = t; idx < HID * CC; idx += TPB) {
            int o = idx >> 6, c = idx & 63;
            W1s[c * 132 + o] = W1[(e * HID + o) * CC + c] * s1[o];
        }
        for (int idx = t; idx < HID * HID; idx += TPB) {
            int o = idx >> 7, i = idx & 127;
            W2s[i * 132 + o] = W2[(e * HID + o) * HID + i] * s2[o];
        }
        for (int idx = t; idx < CC * HID; idx += TPB) {
            int c = idx >> 7, i = idx & 127;
            W3s[i * 68 + c] = W3[(e * CC + c) * HID + i] * gval;
        }
        __syncthreads();
    }

    const float* xb = x + (size_t)b * CC * NPIX;
    float* ob = out + (size_t)b * CC * NPIX;
    const int og  = t >> 3;            // 0..31 -> o block of 4
    const int p8  = (t & 7) * 8;       // 0..56 -> 8 pixels
    const int o0  = og * 4;
    const int cg4 = (t >> 4) * 4;      // 0..60 -> c block of 4 (layer 3)
    const int p4  = (t & 15) * 4;      // 0..60 -> 4 pixels   (layer 3)

    for (int st = 0; st < SUBT; ++st) {
        const int pg0 = chunk * (PX * SUBT) + st * PX;
        __syncthreads();   // previous iteration done reading Xs/H2s
        // ---- stage X tile
        for (int idx = t; idx < CC * (PX / 4); idx += TPB) {
            int c = idx >> 4, j = (idx & 15) * 4;
            *(float4*)&Xs[c * 68 + j] =
                *(const float4*)&xb[(size_t)c * NPIX + pg0 + j];
        }
        __syncthreads();

        // ---- layer 1: H1 = relu(W1' * X + t1)   (4o x 8p per thread)
        {
            unsigned long long acc[4][4];
            #pragma unroll
            for (int i = 0; i < 4; i++)
                #pragma unroll
                for (int j = 0; j < 4; j++) acc[i][j] = 0ull;
            #pragma unroll 4
            for (int c = 0; c < CC; ++c) {
                const float4 w = *(const float4*)&W1s[c * 132 + o0];
                unsigned long long w0 = pk2(w.x, w.x), w1 = pk2(w.y, w.y);
                unsigned long long w2 = pk2(w.z, w.z), w3 = pk2(w.w, w.w);
                const ulonglong2 xa = *(const ulonglong2*)&Xs[c * 68 + p8];
                const ulonglong2 xc = *(const ulonglong2*)&Xs[c * 68 + p8 + 4];
                ffma2(acc[0][0], w0, xa.x); ffma2(acc[0][1], w0, xa.y);
                ffma2(acc[0][2], w0, xc.x); ffma2(acc[0][3], w0, xc.y);
                ffma2(acc[1][0], w1, xa.x); ffma2(acc[1][1], w1, xa.y);
                ffma2(acc[1][2], w1, xc.x); ffma2(acc[1][3], w1, xc.y);
                ffma2(acc[2][0], w2, xa.x); ffma2(acc[2][1], w2, xa.y);
                ffma2(acc[2][2], w2, xc.x); ffma2(acc[2][3], w2, xc.y);
                ffma2(acc[3][0], w3, xa.x); ffma2(acc[3][1], w3, xa.y);
                ffma2(acc[3][2], w3, xc.x); ffma2(acc[3][3], w3, xc.y);
            }
            #pragma unroll
            for (int i = 0; i < 4; i++) {
                const float bb = t1s[o0 + i];
                float2 v0 = up2(acc[i][0]), v1 = up2(acc[i][1]);
                float2 v2 = up2(acc[i][2]), v3 = up2(acc[i][3]);
                *(float4*)&H1s[(o0 + i) * 68 + p8] =
                    make_float4(fmaxf(v0.x + bb, 0.f), fmaxf(v0.y + bb, 0.f),
                                fmaxf(v1.x + bb, 0.f), fmaxf(v1.y + bb, 0.f));
                *(float4*)&H1s[(o0 + i) * 68 + p8 + 4] =
                    make_float4(fmaxf(v2.x + bb, 0.f), fmaxf(v2.y + bb, 0.f),
                                fmaxf(v3.x + bb, 0.f), fmaxf(v3.y + bb, 0.f));
            }
        }
        __syncthreads();

        // ---- layer 2: H2 = relu(W2' * H1 + t2)
        {
            unsigned long long acc[4][4];
            #pragma unroll
            for (int i = 0; i < 4; i++)
                #pragma unroll
                for (int j = 0; j < 4; j++) acc[i][j] = 0ull;
            #pragma unroll 4
            for (int c = 0; c < HID; ++c) {
                const float4 w = *(const float4*)&W2s[c * 132 + o0];
                unsigned long long w0 = pk2(w.x, w.x), w1 = pk2(w.y, w.y);
                unsigned long long w2 = pk2(w.z, w.z), w3 = pk2(w.w, w.w);
                const ulonglong2 xa = *(const ulonglong2*)&H1s[c * 68 + p8];
                const ulonglong2 xc = *(const ulonglong2*)&H1s[c * 68 + p8 + 4];
                ffma2(acc[0][0], w0, xa.x); ffma2(acc[0][1], w0, xa.y);
                ffma2(acc[0][2], w0, xc.x); ffma2(acc[0][3], w0, xc.y);
                ffma2(acc[1][0], w1, xa.x); ffma2(acc[1][1], w1, xa.y);
                ffma2(acc[1][2], w1, xc.x); ffma2(acc[1][3], w1, xc.y);
                ffma2(acc[2][0], w2, xa.x); ffma2(acc[2][1], w2, xa.y);
                ffma2(acc[2][2], w2, xc.x); ffma2(acc[2][3], w2, xc.y);
                ffma2(acc[3][0], w3, xa.x); ffma2(acc[3][1], w3, xa.y);
                ffma2(acc[3][2], w3, xc.x); ffma2(acc[3][3], w3, xc.y);
            }
            #pragma unroll
            for (int i = 0; i < 4; i++) {
                const float bb = t2s[o0 + i];
                float2 v0 = up2(acc[i][0]), v1 = up2(acc[i][1]);
                float2 v2 = up2(acc[i][2]), v3 = up2(acc[i][3]);
                *(float4*)&H2s[(o0 + i) * 68 + p8] =
                    make_float4(fmaxf(v0.x + bb, 0.f), fmaxf(v0.y + bb, 0.f),
                                fmaxf(v1.x + bb, 0.f), fmaxf(v1.y + bb, 0.f));
                *(float4*)&H2s[(o0 + i) * 68 + p8 + 4] =
                    make_float4(fmaxf(v2.x + bb, 0.f), fmaxf(v2.y + bb, 0.f),
                                fmaxf(v3.x + bb, 0.f), fmaxf(v3.y + bb, 0.f));
            }
        }
        __syncthreads();

        // ---- layer 3 + gated combine: out += gval*(W3*H2 + b3)  (4c x 4p)
        {
            unsigned long long acc[4][2];
            #pragma unroll
            for (int i = 0; i < 4; i++) { acc[i][0] = 0ull; acc[i][1] = 0ull; }
            #pragma unroll 4
            for (int i = 0; i < HID; ++i) {
                const float4 w = *(const float4*)&W3s[i * 68 + cg4];
                unsigned long long w0 = pk2(w.x, w.x), w1 = pk2(w.y, w.y);
                unsigned long long w2 = pk2(w.z, w.z), w3 = pk2(w.w, w.w);
                const ulonglong2 xv = *(const ulonglong2*)&H2s[i * 68 + p4];
                ffma2(acc[0][0], w0, xv.x); ffma2(acc[0][1], w0, xv.y);
                ffma2(acc[1][0], w1, xv.x); ffma2(acc[1][1], w1, xv.y);
                ffma2(acc[2][0], w2, xv.x); ffma2(acc[2][1], w2, xv.y);
                ffma2(acc[3][0], w3, xv.x); ffma2(acc[3][1], w3, xv.y);
            }
            #pragma unroll
            for (int ci = 0; ci < 4; ci++) {
                const float bb = b3s[cg4 + ci];
                float2 v0 = up2(acc[ci][0]), v1 = up2(acc[ci][1]);
                float* op = &ob[(size_t)(cg4 + ci) * NPIX + pg0 + p4];
                atomicAdd(op + 0, v0.x + bb);
                atomicAdd(op + 1, v0.y + bb);
                atomicAdd(op + 2, v1.x + bb);
                atomicAdd(op + 3, v1.y + bb);
            }
        }
    }
}

// ---------------------------------------------------------------------------
extern "C" void kernel_launch(void* const* d_in, const int* in_sizes, int n_in,
                              void* d_out, int out_size) {
    const float* x   = (const float*)d_in[0];
    const float* W1  = (const float*)d_in[1];
    const float* b1  = (const float*)d_in[2];
    const float* g1  = (const float*)d_in[3];
    const float* be1 = (const float*)d_in[4];
    const float* m1  = (const float*)d_in[5];
    const float* v1  = (const float*)d_in[6];
    const float* W2  = (const float*)d_in[7];
    const float* b2  = (const float*)d_in[8];
    const float* g2  = (const float*)d_in[9];
    const float* be2 = (const float*)d_in[10];
    const float* m2  = (const float*)d_in[11];
    const float* v2  = (const float*)d_in[12];
    const float* W3  = (const float*)d_in[13];
    const float* b3  = (const float*)d_in[14];
    const float* gw  = (const float*)d_in[15];
    const float* gb  = (const float*)d_in[16];
    float* out = (float*)d_out;

    // zero the image part of the output (aux scalar lives at the end)
    cudaMemsetAsync(out, 0, (size_t)(out_size - 1) * sizeof(float), 0);

    gap_kernel<<<BATCH * CC, TPB>>>(x);
    gate_kernel<<<1, 64>>>(gw, gb, out + (out_size - 1));

    cudaFuncSetAttribute(moe_main, cudaFuncAttributeMaxDynamicSharedMemorySize,
                         SMEM_BYTES);
    dim3 grid(CHUNKS, EE, BATCH);
    moe_main<<<grid, TPB, SMEM_BYTES>>>(x, W1, b1, g1, be1, m1, v1,
                                        W2, b2, g2, be2, m2, v2, W3, b3, out);
}

// round 6
// speedup vs baseline: 1.0019x; 1.0019x over previous
#include <cuda_runtime.h>

#define BATCH 16
#define CC    64
#define HID   128
#define EE    4
#define NPIX  16384      // 128*128
#define PX    64         // pixels per subtile
#define TPB   256
#define CHUNKS 32        // chunks per (b,e); 512 px per chunk
#define SUBT   8         // subtiles per chunk

// SMEM float offsets (strides padded to reduce bank conflicts)
#define OFF_W1  0        // [64][132]
#define OFF_W2  8448     // [128][132]
#define OFF_W3  25344    // [128][68]
#define OFF_T1  34048    // [128]
#define OFF_T2  34176    // [128]
#define OFF_B3  34304    // [64]
#define OFF_X   34368    // [64][68]
#define OFF_H1  38720    // [128][68]
#define OFF_H2  47424    // [128][68]
#define SMEM_FLOATS 56128
#define SMEM_BYTES  (SMEM_FLOATS * 4)

__device__ float g_gap[BATCH * CC];
__device__ float g_gated[BATCH * EE];

// ---------------------------------------------------------------------------
// packed f32x2 helpers (FFMA2: 2x fp32 FMA throughput on sm_103a)
// ---------------------------------------------------------------------------
__device__ __forceinline__ unsigned long long pk2(float a, float b) {
    unsigned long long r;
    asm("mov.b64 %0, {%1, %2};" : "=l"(r) : "f"(a), "f"(b));
    return r;
}
__device__ __forceinline__ void ffma2(unsigned long long& d,
                                      unsigned long long a,
                                      unsigned long long b) {
    asm("fma.rn.f32x2 %0, %1, %2, %0;" : "+l"(d) : "l"(a), "l"(b));
}
__device__ __forceinline__ float2 up2(unsigned long long v) {
    float2 f;
    asm("mov.b64 {%0, %1}, %2;" : "=f"(f.x), "=f"(f.y) : "l"(v));
    return f;
}

// ---------------------------------------------------------------------------
// global average pool: one block per (b,c) row of 16384 pixels
// ---------------------------------------------------------------------------
__global__ void gap_kernel(const float* __restrict__ x) {
    const int bc = blockIdx.x;
    const float4* p = (const float4*)(x + (size_t)bc * NPIX);
    float s = 0.f;
    for (int i = threadIdx.x; i < NPIX / 4; i += TPB) {
        float4 v = p[i];
        s += (v.x + v.y) + (v.z + v.w);
    }
    #pragma unroll
    for (int o = 16; o; o >>= 1) s += __shfl_down_sync(0xffffffffu, s, o);
    __shared__ float red[8];
    if ((threadIdx.x & 31) == 0) red[threadIdx.x >> 5] = s;
    __syncthreads();
    if (threadIdx.x == 0) {
        float tot = 0.f;
        #pragma unroll
        for (int i = 0; i < 8; i++) tot += red[i];
        g_gap[bc] = tot * (1.f / NPIX);
    }
}

// ---------------------------------------------------------------------------
// gate: logits -> softmax -> top2 -> normalized gated weights + aux loss
// ---------------------------------------------------------------------------
__global__ void gate_kernel(const float* __restrict__ gw,
                            const float* __restrict__ gb,
                            float* __restrict__ aux_out) {
    __shared__ float logit_s[BATCH][EE];
    __shared__ float gsh[BATCH][EE];
    const int t = threadIdx.x;
    if (t < BATCH * EE) {
        const int b = t >> 2, e = t & 3;
        float s = gb[e];
        const float* gp = g_gap + b * CC;
        #pragma unroll 8
        for (int c = 0; c < CC; c++) s += gp[c] * gw[e * CC + c];
        logit_s[b][e] = s;
    }
    __syncthreads();
    if (t < BATCH) {
        const int b = t;
        float l[EE];
        float mx = -1e30f;
        #pragma unroll
        for (int e = 0; e < EE; e++) { l[e] = logit_s[b][e]; mx = fmaxf(mx, l[e]); }
        float sum = 0.f;
        #pragma unroll
        for (int e = 0; e < EE; e++) { l[e] = expf(l[e] - mx); sum += l[e]; }
        #pragma unroll
        for (int e = 0; e < EE; e++) l[e] /= sum;
        // top-2 (ties -> lower index, matching jax top_k)
        int i1 = 0;
        for (int e = 1; e < EE; e++) if (l[e] > l[i1]) i1 = e;
        int i2 = -1;
        for (int e = 0; e < EE; e++) {
            if (e == i1) continue;
            if (i2 < 0 || l[e] > l[i2]) i2 = e;
        }
        const float denom = l[i1] + l[i2] + 1e-8f;
        #pragma unroll
        for (int e = 0; e < EE; e++) {
            float gv = (e == i1 || e == i2) ? l[e] / denom : 0.f;
            gsh[b][e] = gv;
            g_gated[b * EE + e] = gv;
        }
    }
    __syncthreads();
    if (t == 0) {
        float u[EE];
        float mean = 0.f;
        #pragma unroll
        for (int e = 0; e < EE; e++) {
            float s = 0.f;
            for (int b = 0; b < BATCH; b++) s += gsh[b][e];
            u[e] = s;
            mean += s;
        }
        mean *= (1.f / EE);
        float var = 0.f;
        #pragma unroll
        for (int e = 0; e < EE; e++) { float d = u[e] - mean; var += d * d; }
        var *= (1.f / EE);
        *aux_out = var / (mean * mean + 1e-10f);
    }
}

// ---------------------------------------------------------------------------
// fused 3-layer expert: one CTA per (chunk, expert, batch); skips gated==0
// ---------------------------------------------------------------------------
__global__ __launch_bounds__(TPB, 1)
void moe_main(const float* __restrict__ x,
              const float* __restrict__ W1, const float* __restrict__ b1,
              const float* __restrict__ g1, const float* __restrict__ be1,
              const float* __restrict__ m1, const float* __restrict__ v1,
              const float* __restrict__ W2, const float* __restrict__ b2,
              const float* __restrict__ g2, const float* __restrict__ be2,
              const float* __restrict__ m2, const float* __restrict__ v2,
              const float* __restrict__ W3, const float* __restrict__ b3,
              float* __restrict__ out) {
    extern __shared__ float sm[];
    const int chunk = blockIdx.x;
    const int e     = blockIdx.y;
    const int b     = blockIdx.z;
    const float gval = g_gated[b * EE + e];
    if (gval == 0.f) return;

    float* W1s = sm + OFF_W1;   // [c][132] BN-folded
    float* W2s = sm + OFF_W2;   // [i][132] BN-folded
    float* W3s = sm + OFF_W3;   // [i][68]  gate-folded
    float* t1s = sm + OFF_T1;
    float* t2s = sm + OFF_T2;
    float* b3s = sm + OFF_B3;
    float* Xs  = sm + OFF_X;    // [c][68]
    float* H1s = sm + OFF_H1;   // [o][68]
    float* H2s = sm + OFF_H2;   // [o][68]
    const int t = threadIdx.x;

    // ---- load + fold weights (BN eval-mode fold, gate-weight fold into W3/b3)
    {
        float* s1 = Xs;         // temp scale storage (Xs unused yet)
        float* s2 = Xs + 128;
        for (int o = t; o < HID; o += TPB) {
            float inv1 = g1[e * HID + o] * rsqrtf(v1[e * HID + o] + 1e-5f);
            s1[o] = inv1;
            t1s[o] = (b1[e * HID + o] - m1[e * HID + o]) * inv1 + be1[e * HID + o];
            float inv2 = g2[e * HID + o] * rsqrtf(v2[e * HID + o] + 1e-5f);
            s2[o] = inv2;
            t2s[o] = (b2[e * HID + o] - m2[e * HID + o]) * inv2 + be2[e * HID + o];
        }
        for (int c = t; c < CC; c += TPB) b3s[c] = b3[e * CC + c] * gval;
        __syncthreads();
        for (int idx = t; idx < HID * CC; idx += TPB) {
            int o = idx >> 6, c = idx & 63;
            W1s[c * 132 + o] = W1[(e * HID + o) * CC + c] * s1[o];
        }
        for (int idx = t; idx < HID * HID; idx += TPB) {
            int o = idx >> 7, i = idx & 127;
            W2s[i * 132 + o] = W2[(e * HID + o) * HID + i] * s2[o];
        }
        for (int idx = t; idx < CC * HID; idx += TPB) {
            int c = idx >> 7, i = idx & 127;
            W3s[i * 68 + c] = W3[(e * CC + c) * HID + i] * gval;
        }
        __syncthreads();
    }

    const float* xb = x + (size_t)b * CC * NPIX;
    float* ob = out + (size_t)b * CC * NPIX;
    const int og  = t >> 3;            // 0..31 -> o block of 4
    const int p8  = (t & 7) * 8;       // 0..56 -> 8 pixels
    const int o0  = og * 4;
    const int cg4 = (t >> 4) * 4;      // 0..60 -> c block of 4 (layer 3)
    const int p4  = (t & 15) * 4;      // 0..60 -> 4 pixels   (layer 3)

    for (int st = 0; st < SUBT; ++st) {
        const int pg0 = chunk * (PX * SUBT) + st * PX;
        __syncthreads();   // previous iteration done reading Xs/H2s
        // ---- stage X tile
        for (int idx = t; idx < CC * (PX / 4); idx += TPB) {
            int c = idx >> 4, j = (idx & 15) * 4;
            *(float4*)&Xs[c * 68 + j] =
                *(const float4*)&xb[(size_t)c * NPIX + pg0 + j];
        }
        __syncthreads();

        // ---- layer 1: H1 = relu(W1' * X + t1)   (4o x 8p per thread)
        {
            unsigned long long acc[4][4];
            #pragma unroll
            for (int i = 0; i < 4; i++)
                #pragma unroll
                for (int j = 0; j < 4; j++) acc[i][j] = 0ull;
            #pragma unroll 4
            for (int c = 0; c < CC; ++c) {
                const float4 w = *(const float4*)&W1s[c * 132 + o0];
                unsigned long long w0 = pk2(w.x, w.x), w1 = pk2(w.y, w.y);
                unsigned long long w2 = pk2(w.z, w.z), w3 = pk2(w.w, w.w);
                const ulonglong2 xa = *(const ulonglong2*)&Xs[c * 68 + p8];
                const ulonglong2 xc = *(const ulonglong2*)&Xs[c * 68 + p8 + 4];
                ffma2(acc[0][0], w0, xa.x); ffma2(acc[0][1], w0, xa.y);
                ffma2(acc[0][2], w0, xc.x); ffma2(acc[0][3], w0, xc.y);
                ffma2(acc[1][0], w1, xa.x); ffma2(acc[1][1], w1, xa.y);
                ffma2(acc[1][2], w1, xc.x); ffma2(acc[1][3], w1, xc.y);
                ffma2(acc[2][0], w2, xa.x); ffma2(acc[2][1], w2, xa.y);
                ffma2(acc[2][2], w2, xc.x); ffma2(acc[2][3], w2, xc.y);
                ffma2(acc[3][0], w3, xa.x); ffma2(acc[3][1], w3, xa.y);
                ffma2(acc[3][2], w3, xc.x); ffma2(acc[3][3], w3, xc.y);
            }
            #pragma unroll
            for (int i = 0; i < 4; i++) {
                const float bb = t1s[o0 + i];
                float2 v0 = up2(acc[i][0]), v1 = up2(acc[i][1]);
                float2 v2 = up2(acc[i][2]), v3 = up2(acc[i][3]);
                *(float4*)&H1s[(o0 + i) * 68 + p8] =
                    make_float4(fmaxf(v0.x + bb, 0.f), fmaxf(v0.y + bb, 0.f),
                                fmaxf(v1.x + bb, 0.f), fmaxf(v1.y + bb, 0.f));
                *(float4*)&H1s[(o0 + i) * 68 + p8 + 4] =
                    make_float4(fmaxf(v2.x + bb, 0.f), fmaxf(v2.y + bb, 0.f),
                                fmaxf(v3.x + bb, 0.f), fmaxf(v3.y + bb, 0.f));
            }
        }
        __syncthreads();

        // ---- layer 2: H2 = relu(W2' * H1 + t2)
        {
            unsigned long long acc[4][4];
            #pragma unroll
            for (int i = 0; i < 4; i++)
                #pragma unroll
                for (int j = 0; j < 4; j++) acc[i][j] = 0ull;
            #pragma unroll 4
            for (int c = 0; c < HID; ++c) {
                const float4 w = *(const float4*)&W2s[c * 132 + o0];
                unsigned long long w0 = pk2(w.x, w.x), w1 = pk2(w.y, w.y);
                unsigned long long w2 = pk2(w.z, w.z), w3 = pk2(w.w, w.w);
                const ulonglong2 xa = *(const ulonglong2*)&H1s[c * 68 + p8];
                const ulonglong2 xc = *(const ulonglong2*)&H1s[c * 68 + p8 + 4];
                ffma2(acc[0][0], w0, xa.x); ffma2(acc[0][1], w0, xa.y);
                ffma2(acc[0][2], w0, xc.x); ffma2(acc[0][3], w0, xc.y);
                ffma2(acc[1][0], w1, xa.x); ffma2(acc[1][1], w1, xa.y);
                ffma2(acc[1][2], w1, xc.x); ffma2(acc[1][3], w1, xc.y);
                ffma2(acc[2][0], w2, xa.x); ffma2(acc[2][1], w2, xa.y);
                ffma2(acc[2][2], w2, xc.x); ffma2(acc[2][3], w2, xc.y);
                ffma2(acc[3][0], w3, xa.x); ffma2(acc[3][1], w3, xa.y);
                ffma2(acc[3][2], w3, xc.x); ffma2(acc[3][3], w3, xc.y);
            }
            #pragma unroll
            for (int i = 0; i < 4; i++) {
                const float bb = t2s[o0 + i];
                float2 v0 = up2(acc[i][0]), v1 = up2(acc[i][1]);
                float2 v2 = up2(acc[i][2]), v3 = up2(acc[i][3]);
                *(float4*)&H2s[(o0 + i) * 68 + p8] =
                    make_float4(fmaxf(v0.x + bb, 0.f), fmaxf(v0.y + bb, 0.f),
                                fmaxf(v1.x + bb, 0.f), fmaxf(v1.y + bb, 0.f));
                *(float4*)&H2s[(o0 + i) * 68 + p8 + 4] =
                    make_float4(fmaxf(v2.x + bb, 0.f), fmaxf(v2.y + bb, 0.f),
                                fmaxf(v3.x + bb, 0.f), fmaxf(v3.y + bb, 0.f));
            }
        }
        __syncthreads();

        // ---- layer 3 + gated combine: out += gval*(W3*H2 + b3)  (4c x 4p)
        {
            unsigned long long acc[4][2];
            #pragma unroll
            for (int i = 0; i < 4; i++) { acc[i][0] = 0ull; acc[i][1] = 0ull; }
            #pragma unroll 4
            for (int i = 0; i < HID; ++i) {
                const float4 w = *(const float4*)&W3s[i * 68 + cg4];
                unsigned long long w0 = pk2(w.x, w.x), w1 = pk2(w.y, w.y);
                unsigned long long w2 = pk2(w.z, w.z), w3 = pk2(w.w, w.w);
                const ulonglong2 xv = *(const ulonglong2*)&H2s[i * 68 + p4];
                ffma2(acc[0][0], w0, xv.x); ffma2(acc[0][1], w0, xv.y);
                ffma2(acc[1][0], w1, xv.x); ffma2(acc[1][1], w1, xv.y);
                ffma2(acc[2][0], w2, xv.x); ffma2(acc[2][1], w2, xv.y);
                ffma2(acc[3][0], w3, xv.x); ffma2(acc[3][1], w3, xv.y);
            }
            #pragma unroll
            for (int ci = 0; ci < 4; ci++) {
                const float bb = b3s[cg4 + ci];
                float2 v0 = up2(acc[ci][0]), v1 = up2(acc[ci][1]);
                float* op = &ob[(size_t)(cg4 + ci) * NPIX + pg0 + p4];
                atomicAdd(op + 0, v0.x + bb);
                atomicAdd(op + 1, v0.y + bb);
                atomicAdd(op + 2, v1.x + bb);
                atomicAdd(op + 3, v1.y + bb);
            }
        }
    }
}

// ---------------------------------------------------------------------------
extern "C" void kernel_launch(void* const* d_in, const int* in_sizes, int n_in,
                              void* d_out, int out_size) {
    const float* x   = (const float*)d_in[0];
    const float* W1  = (const float*)d_in[1];
    const float* b1  = (const float*)d_in[2];
    const float* g1  = (const float*)d_in[3];
    const float* be1 = (const float*)d_in[4];
    const float* m1  = (const float*)d_in[5];
    const float* v1  = (const float*)d_in[6];
    const float* W2  = (const float*)d_in[7];
    const float* b2  = (const float*)d_in[8];
    const float* g2  = (const float*)d_in[9];
    const float* be2 = (const float*)d_in[10];
    const float* m2  = (const float*)d_in[11];
    const float* v2  = (const float*)d_in[12];
    const float* W3  = (const float*)d_in[13];
    const float* b3  = (const float*)d_in[14];
    const float* gw  = (const float*)d_in[15];
    const float* gb  = (const float*)d_in[16];
    float* out = (float*)d_out;

    // zero the image part of the output (aux scalar lives at the end)
    cudaMemsetAsync(out, 0, (size_t)(out_size - 1) * sizeof(float), 0);

    gap_kernel<<<BATCH * CC, TPB>>>(x);
    gate_kernel<<<1, 64>>>(gw, gb, out + (out_size - 1));

    cudaFuncSetAttribute(moe_main, cudaFuncAttributeMaxDynamicSharedMemorySize,
                         SMEM_BYTES);
    dim3 grid(CHUNKS, EE, BATCH);
    moe_main<<<grid, TPB, SMEM_BYTES>>>(x, W1, b1, g1, be1, m1, v1,
                                        W2, b2, g2, be2, m2, v2, W3, b3, out);
}

// round 7
// speedup vs baseline: 1.0023x; 1.0005x over previous
#include <cuda_runtime.h>

#define BATCH 16
#define CC    64
#define HID   128
#define EE    4
#define NPIX  16384      // 128*128
#define PX    64         // pixels per subtile
#define TPB   256
#define CHUNKS 32        // chunks per (b,e); 512 px per chunk
#define SUBT   8         // subtiles per chunk

// SMEM float offsets (strides padded to reduce bank conflicts)
#define OFF_W1  0        // [64][132]
#define OFF_W2  8448     // [128][132]
#define OFF_W3  25344    // [128][68]
#define OFF_T1  34048    // [128]
#define OFF_T2  34176    // [128]
#define OFF_B3  34304    // [64]
#define OFF_X   34368    // [64][68]
#define OFF_H1  38720    // [128][68]
#define OFF_H2  47424    // [128][68]
#define SMEM_FLOATS 56128
#define SMEM_BYTES  (SMEM_FLOATS * 4)

__device__ float g_gap[BATCH * CC];
__device__ float g_gated[BATCH * EE];

// ---------------------------------------------------------------------------
// packed f32x2 helpers (FFMA2: 2x fp32 FMA throughput on sm_103a)
// ---------------------------------------------------------------------------
__device__ __forceinline__ unsigned long long pk2(float a, float b) {
    unsigned long long r;
    asm("mov.b64 %0, {%1, %2};" : "=l"(r) : "f"(a), "f"(b));
    return r;
}
__device__ __forceinline__ void ffma2(unsigned long long& d,
                                      unsigned long long a,
                                      unsigned long long b) {
    asm("fma.rn.f32x2 %0, %1, %2, %0;" : "+l"(d) : "l"(a), "l"(b));
}
__device__ __forceinline__ float2 up2(unsigned long long v) {
    float2 f;
    asm("mov.b64 {%0, %1}, %2;" : "=f"(f.x), "=f"(f.y) : "l"(v));
    return f;
}

// ---------------------------------------------------------------------------
// global average pool: one block per (b,c) row of 16384 pixels
// ---------------------------------------------------------------------------
__global__ void gap_kernel(const float* __restrict__ x) {
    const int bc = blockIdx.x;
    const float4* p = (const float4*)(x + (size_t)bc * NPIX);
    float s = 0.f;
    for (int i = threadIdx.x; i < NPIX / 4; i += TPB) {
        float4 v = p[i];
        s += (v.x + v.y) + (v.z + v.w);
    }
    #pragma unroll
    for (int o = 16; o; o >>= 1) s += __shfl_down_sync(0xffffffffu, s, o);
    __shared__ float red[8];
    if ((threadIdx.x & 31) == 0) red[threadIdx.x >> 5] = s;
    __syncthreads();
    if (threadIdx.x == 0) {
        float tot = 0.f;
        #pragma unroll
        for (int i = 0; i < 8; i++) tot += red[i];
        g_gap[bc] = tot * (1.f / NPIX);
    }
}

// ---------------------------------------------------------------------------
// gate: logits -> softmax -> top2 -> normalized gated weights + aux loss
// ---------------------------------------------------------------------------
__global__ void gate_kernel(const float* __restrict__ gw,
                            const float* __restrict__ gb,
                            float* __restrict__ aux_out) {
    __shared__ float logit_s[BATCH][EE];
    __shared__ float gsh[BATCH][EE];
    const int t = threadIdx.x;
    if (t < BATCH * EE) {
        const int b = t >> 2, e = t & 3;
        float s = gb[e];
        const float* gp = g_gap + b * CC;
        #pragma unroll 8
        for (int c = 0; c < CC; c++) s += gp[c] * gw[e * CC + c];
        logit_s[b][e] = s;
    }
    __syncthreads();
    if (t < BATCH) {
        const int b = t;
        float l[EE];
        float mx = -1e30f;
        #pragma unroll
        for (int e = 0; e < EE; e++) { l[e] = logit_s[b][e]; mx = fmaxf(mx, l[e]); }
        float sum = 0.f;
        #pragma unroll
        for (int e = 0; e < EE; e++) { l[e] = expf(l[e] - mx); sum += l[e]; }
        #pragma unroll
        for (int e = 0; e < EE; e++) l[e] /= sum;
        // top-2 (ties -> lower index, matching jax top_k)
        int i1 = 0;
        for (int e = 1; e < EE; e++) if (l[e] > l[i1]) i1 = e;
        int i2 = -1;
        for (int e = 0; e < EE; e++) {
            if (e == i1) continue;
            if (i2 < 0 || l[e] > l[i2]) i2 = e;
        }
        const float denom = l[i1] + l[i2] + 1e-8f;
        #pragma unroll
        for (int e = 0; e < EE; e++) {
            float gv = (e == i1 || e == i2) ? l[e] / denom : 0.f;
            gsh[b][e] = gv;
            g_gated[b * EE + e] = gv;
        }
    }
    __syncthreads();
    if (t == 0) {
        float u[EE];
        float mean = 0.f;
        #pragma unroll
        for (int e = 0; e < EE; e++) {
            float s = 0.f;
            for (int b = 0; b < BATCH; b++) s += gsh[b][e];
            u[e] = s;
            mean += s;
        }
        mean *= (1.f / EE);
        float var = 0.f;
        #pragma unroll
        for (int e = 0; e < EE; e++) { float d = u[e] - mean; var += d * d; }
        var *= (1.f / EE);
        *aux_out = var / (mean * mean + 1e-10f);
    }
}

// ---------------------------------------------------------------------------
// fused 3-layer expert: one CTA per (chunk, expert, batch); skips gated==0
// ---------------------------------------------------------------------------
__global__ __launch_bounds__(TPB, 1)
void moe_main(const float* __restrict__ x,
              const float* __restrict__ W1, const float* __restrict__ b1,
              const float* __restrict__ g1, const float* __restrict__ be1,
              const float* __restrict__ m1, const float* __restrict__ v1,
              const float* __restrict__ W2, const float* __restrict__ b2,
              const float* __restrict__ g2, const float* __restrict__ be2,
              const float* __restrict__ m2, const float* __restrict__ v2,
              const float* __restrict__ W3, const float* __restrict__ b3,
              float* __restrict__ out) {
    extern __shared__ float sm[];
    const int chunk = blockIdx.x;
    const int e     = blockIdx.y;
    const int b     = blockIdx.z;
    const float gval = g_gated[b * EE + e];
    if (gval == 0.f) return;

    float* W1s = sm + OFF_W1;   // [c][132] BN-folded
    float* W2s = sm + OFF_W2;   // [i][132] BN-folded
    float* W3s = sm + OFF_W3;   // [i][68]  gate-folded
    float* t1s = sm + OFF_T1;
    float* t2s = sm + OFF_T2;
    float* b3s = sm + OFF_B3;
    float* Xs  = sm + OFF_X;    // [c][68]
    float* H1s = sm + OFF_H1;   // [o][68]
    float* H2s = sm + OFF_H2;   // [o][68]
    const int t = threadIdx.x;

    // ---- load + fold weights (BN eval-mode fold, gate-weight fold into W3/b3)
    {
        float* s1 = Xs;         // temp scale storage (Xs unused yet)
        float* s2 = Xs + 128;
        for (int o = t; o < HID; o += TPB) {
            float inv1 = g1[e * HID + o] * rsqrtf(v1[e * HID + o] + 1e-5f);
            s1[o] = inv1;
            t1s[o] = (b1[e * HID + o] - m1[e * HID + o]) * inv1 + be1[e * HID + o];
            float inv2 = g2[e * HID + o] * rsqrtf(v2[e * HID + o] + 1e-5f);
            s2[o] = inv2;
            t2s[o] = (b2[e * HID + o] - m2[e * HID + o]) * inv2 + be2[e * HID + o];
        }
        for (int c = t; c < CC; c += TPB) b3s[c] = b3[e * CC + c] * gval;
        __syncthreads();
        for (int idx = t; idx < HID * CC; idx += TPB) {
            int o = idx >> 6, c = idx & 63;
            W1s[c * 132 + o] = W1[(e * HID + o) * CC + c] * s1[o];
        }
        for (int idx = t; idx < HID * HID; idx += TPB) {
            int o = idx >> 7, i = idx & 127;
            W2s[i * 132 + o] = W2[(e * HID + o) * HID + i] * s2[o];
        }
        for (int idx = t; idx < CC * HID; idx += TPB) {
            int c = idx >> 7, i = idx & 127;
            W3s[i * 68 + c] = W3[(e * CC + c) * HID + i] * gval;
        }
        __syncthreads();
    }

    const float* xb = x + (size_t)b * CC * NPIX;
    float* ob = out + (size_t)b * CC * NPIX;
    const int og  = t >> 3;            // 0..31 -> o block of 4
    const int p8  = (t & 7) * 8;       // 0..56 -> 8 pixels
    const int o0  = og * 4;
    const int cg4 = (t >> 4) * 4;      // 0..60 -> c block of 4 (layer 3)
    const int p4  = (t & 15) * 4;      // 0..60 -> 4 pixels   (layer 3)

    for (int st = 0; st < SUBT; ++st) {
        const int pg0 = chunk * (PX * SUBT) + st * PX;
        __syncthreads();   // previous iteration done reading Xs/H2s
        // ---- stage X tile
        for (int idx = t; idx < CC * (PX / 4); idx += TPB) {
            int c = idx >> 4, j = (idx & 15) * 4;
            *(float4*)&Xs[c * 68 + j] =
                *(const float4*)&xb[(size_t)c * NPIX + pg0 + j];
        }
        __syncthreads();

        // ---- layer 1: H1 = relu(W1' * X + t1)   (4o x 8p per thread)
        {
            unsigned long long acc[4][4];
            #pragma unroll
            for (int i = 0; i < 4; i++)
                #pragma unroll
                for (int j = 0; j < 4; j++) acc[i][j] = 0ull;
            #pragma unroll 4
            for (int c = 0; c < CC; ++c) {
                const float4 w = *(const float4*)&W1s[c * 132 + o0];
                unsigned long long w0 = pk2(w.x, w.x), w1 = pk2(w.y, w.y);
                unsigned long long w2 = pk2(w.z, w.z), w3 = pk2(w.w, w.w);
                const ulonglong2 xa = *(const ulonglong2*)&Xs[c * 68 + p8];
                const ulonglong2 xc = *(const ulonglong2*)&Xs[c * 68 + p8 + 4];
                ffma2(acc[0][0], w0, xa.x); ffma2(acc[0][1], w0, xa.y);
                ffma2(acc[0][2], w0, xc.x); ffma2(acc[0][3], w0, xc.y);
                ffma2(acc[1][0], w1, xa.x); ffma2(acc[1][1], w1, xa.y);
                ffma2(acc[1][2], w1, xc.x); ffma2(acc[1][3], w1, xc.y);
                ffma2(acc[2][0], w2, xa.x); ffma2(acc[2][1], w2, xa.y);
                ffma2(acc[2][2], w2, xc.x); ffma2(acc[2][3], w2, xc.y);
                ffma2(acc[3][0], w3, xa.x); ffma2(acc[3][1], w3, xa.y);
                ffma2(acc[3][2], w3, xc.x); ffma2(acc[3][3], w3, xc.y);
            }
            #pragma unroll
            for (int i = 0; i < 4; i++) {
                const float bb = t1s[o0 + i];
                float2 v0 = up2(acc[i][0]), v1 = up2(acc[i][1]);
                float2 v2 = up2(acc[i][2]), v3 = up2(acc[i][3]);
                *(float4*)&H1s[(o0 + i) * 68 + p8] =
                    make_float4(fmaxf(v0.x + bb, 0.f), fmaxf(v0.y + bb, 0.f),
                                fmaxf(v1.x + bb, 0.f), fmaxf(v1.y + bb, 0.f));
                *(float4*)&H1s[(o0 + i) * 68 + p8 + 4] =
                    make_float4(fmaxf(v2.x + bb, 0.f), fmaxf(v2.y + bb, 0.f),
                                fmaxf(v3.x + bb, 0.f), fmaxf(v3.y + bb, 0.f));
            }
        }
        __syncthreads();

        // ---- layer 2: H2 = relu(W2' * H1 + t2)
        {
            unsigned long long acc[4][4];
            #pragma unroll
            for (int i = 0; i < 4; i++)
                #pragma unroll
                for (int j = 0; j < 4; j++) acc[i][j] = 0ull;
            #pragma unroll 4
            for (int c = 0; c < HID; ++c) {
                const float4 w = *(const float4*)&W2s[c * 132 + o0];
                unsigned long long w0 = pk2(w.x, w.x), w1 = pk2(w.y, w.y);
                unsigned long long w2 = pk2(w.z, w.z), w3 = pk2(w.w, w.w);
                const ulonglong2 xa = *(const ulonglong2*)&H1s[c * 68 + p8];
                const ulonglong2 xc = *(const ulonglong2*)&H1s[c * 68 + p8 + 4];
                ffma2(acc[0][0], w0, xa.x); ffma2(acc[0][1], w0, xa.y);
                ffma2(acc[0][2], w0, xc.x); ffma2(acc[0][3], w0, xc.y);
                ffma2(acc[1][0], w1, xa.x); ffma2(acc[1][1], w1, xa.y);
                ffma2(acc[1][2], w1, xc.x); ffma2(acc[1][3], w1, xc.y);
                ffma2(acc[2][0], w2, xa.x); ffma2(acc[2][1], w2, xa.y);
                ffma2(acc[2][2], w2, xc.x); ffma2(acc[2][3], w2, xc.y);
                ffma2(acc[3][0], w3, xa.x); ffma2(acc[3][1], w3, xa.y);
                ffma2(acc[3][2], w3, xc.x); ffma2(acc[3][3], w3, xc.y);
            }
            #pragma unroll
            for (int i = 0; i < 4; i++) {
                const float bb = t2s[o0 + i];
                float2 v0 = up2(acc[i][0]), v1 = up2(acc[i][1]);
                float2 v2 = up2(acc[i][2]), v3 = up2(acc[i][3]);
                *(float4*)&H2s[(o0 + i) * 68 + p8] =
                    make_float4(fmaxf(v0.x + bb, 0.f), fmaxf(v0.y + bb, 0.f),
                                fmaxf(v1.x + bb, 0.f), fmaxf(v1.y + bb, 0.f));
                *(float4*)&H2s[(o0 + i) * 68 + p8 + 4] =
                    make_float4(fmaxf(v2.x + bb, 0.f), fmaxf(v2.y + bb, 0.f),
                                fmaxf(v3.x + bb, 0.f), fmaxf(v3.y + bb, 0.f));
            }
        }
        __syncthreads();

        // ---- layer 3 + gated combine: out += gval*(W3*H2 + b3)  (4c x 4p)
        {
            unsigned long long acc[4][2];
            #pragma unroll
            for (int i = 0; i < 4; i++) { acc[i][0] = 0ull; acc[i][1] = 0ull; }
            #pragma unroll 4
            for (int i = 0; i < HID; ++i) {
                const float4 w = *(const float4*)&W3s[i * 68 + cg4];
                unsigned long long w0 = pk2(w.x, w.x), w1 = pk2(w.y, w.y);
                unsigned long long w2 = pk2(w.z, w.z), w3 = pk2(w.w, w.w);
                const ulonglong2 xv = *(const ulonglong2*)&H2s[i * 68 + p4];
                ffma2(acc[0][0], w0, xv.x); ffma2(acc[0][1], w0, xv.y);
                ffma2(acc[1][0], w1, xv.x); ffma2(acc[1][1], w1, xv.y);
                ffma2(acc[2][0], w2, xv.x); ffma2(acc[2][1], w2, xv.y);
                ffma2(acc[3][0], w3, xv.x); ffma2(acc[3][1], w3, xv.y);
            }
            #pragma unroll
            for (int ci = 0; ci < 4; ci++) {
                const float bb = b3s[cg4 + ci];
                float2 v0 = up2(acc[ci][0]), v1 = up2(acc[ci][1]);
                float* op = &ob[(size_t)(cg4 + ci) * NPIX + pg0 + p4];
                atomicAdd(op + 0, v0.x + bb);
                atomicAdd(op + 1, v0.y + bb);
                atomicAdd(op + 2, v1.x + bb);
                atomicAdd(op + 3, v1.y + bb);
            }
        }
    }
}

// ---------------------------------------------------------------------------
extern "C" void kernel_launch(void* const* d_in, const int* in_sizes, int n_in,
                              void* d_out, int out_size) {
    const float* x   = (const float*)d_in[0];
    const float* W1  = (const float*)d_in[1];
    const float* b1  = (const float*)d_in[2];
    const float* g1  = (const float*)d_in[3];
    const float* be1 = (const float*)d_in[4];
    const float* m1  = (const float*)d_in[5];
    const float* v1  = (const float*)d_in[6];
    const float* W2  = (const float*)d_in[7];
    const float* b2  = (const float*)d_in[8];
    const float* g2  = (const float*)d_in[9];
    const float* be2 = (const float*)d_in[10];
    const float* m2  = (const float*)d_in[11];
    const float* v2  = (const float*)d_in[12];
    const float* W3  = (const float*)d_in[13];
    const float* b3  = (const float*)d_in[14];
    const float* gw  = (const float*)d_in[15];
    const float* gb  = (const float*)d_in[16];
    float* out = (float*)d_out;

    // zero the image part of the output (aux scalar lives at the end)
    cudaMemsetAsync(out, 0, (size_t)(out_size - 1) * sizeof(float), 0);

    gap_kernel<<<BATCH * CC, TPB>>>(x);
    gate_kernel<<<1, 64>>>(gw, gb, out + (out_size - 1));

    cudaFuncSetAttribute(moe_main, cudaFuncAttributeMaxDynamicSharedMemorySize,
                         SMEM_BYTES);
    dim3 grid(CHUNKS, EE, BATCH);
    moe_main<<<grid, TPB, SMEM_BYTES>>>(x, W1, b1, g1, be1, m1, v1,
                                        W2, b2, g2, be2, m2, v2, W3, b3, out);
}

// round 10
// speedup vs baseline: 2.7067x; 2.7004x over previous
#include <cuda_runtime.h>
#include <cuda_bf16.h>
#include <cstdint>

#define BATCH 16
#define CC    64
#define HID   128
#define EE    4
#define NPIX  16384
#define TPB   256
#define NCHUNK 16
#define TILES_PER_CTA 16
#define TILE_PX 64

// strides (bf16 elements)
#define SD64  72      // rows with 64 valid cols
#define SD128 136     // rows with 128 valid cols

// SMEM byte offsets (16B aligned; ldmatrix row addresses 16B aligned)
#define S_W1H 0                 // [128 out][72] bf16 = 18432
#define S_W1L 18432
#define S_W2H 36864             // [128][136] = 34816
#define S_W2L 71680
#define S_W3H 106496            // [64][136] = 17408
#define S_W3L 123904
#define S_H1H 141312            // [64 px][136] = 17408
#define S_H1L 158720
#define S_H2H 176128            // [64 px][136]; X tile [64 px][72] overlays
#define S_H2L 193536
#define S_T1  210944            // float[128]
#define S_T2  211456            // float[128]
#define S_B3  211968            // float[64]
#define SMEM_BYTES 212224

// ---------------- persistent prepped data ----------------------------------
__device__ unsigned short g_w1h[EE * 8192],  g_w1l[EE * 8192];   // [o128][i64]
__device__ unsigned short g_w2h[EE * 16384], g_w2l[EE * 16384];  // [o128][i128]
__device__ unsigned short g_w3h[EE * 8192],  g_w3l[EE * 8192];   // [c64][i128]
__device__ float g_t1[EE * HID], g_t2[EE * HID];
__device__ float g_gap[BATCH * CC];
__device__ float g_gated[BATCH * EE];

// ---------------- helpers ---------------------------------------------------
__device__ __forceinline__ uint32_t smem_u32(const void* p) {
    uint32_t a;
    asm("{ .reg .u64 t; cvta.to.shared.u64 t, %1; cvt.u32.u64 %0, t; }"
        : "=r"(a) : "l"(p));
    return a;
}
// pack (a,b) -> bf16x2 hi + bf16x2 residual-lo (a -> low half)
__device__ __forceinline__ void split2(float a, float b, uint32_t& h, uint32_t& l) {
    asm("cvt.rn.bf16x2.f32 %0, %1, %2;" : "=r"(h) : "f"(b), "f"(a));
    float ha = __uint_as_float(h << 16);
    float hb = __uint_as_float(h & 0xffff0000u);
    asm("cvt.rn.bf16x2.f32 %0, %1, %2;" : "=r"(l) : "f"(b - hb), "f"(a - ha));
}
__device__ __forceinline__ void split1(float a, unsigned short& h, unsigned short& l) {
    __nv_bfloat16 hb = __float2bfloat16(a);
    h = __bfloat16_as_ushort(hb);
    l = __bfloat16_as_ushort(__float2bfloat16(a - __bfloat162float(hb)));
}

#define LDSM4(R, ADDR) asm volatile( \
    "ldmatrix.sync.aligned.m8n8.x4.shared.b16 {%0,%1,%2,%3}, [%4];" \
    : "=r"((R)[0]), "=r"((R)[1]), "=r"((R)[2]), "=r"((R)[3]) : "r"(ADDR))
#define LDSM2(R, ADDR) asm volatile( \
    "ldmatrix.sync.aligned.m8n8.x2.shared.b16 {%0,%1}, [%2];" \
    : "=r"((R)[0]), "=r"((R)[1]) : "r"(ADDR))
#define MMA(D, A, B) asm volatile( \
    "mma.sync.aligned.m16n8k16.row.col.f32.bf16.bf16.f32 " \
    "{%0,%1,%2,%3}, {%4,%5,%6,%7}, {%8,%9}, {%0,%1,%2,%3};" \
    : "+f"((D)[0]), "+f"((D)[1]), "+f"((D)[2]), "+f"((D)[3]) \
    : "r"((A)[0]), "r"((A)[1]), "r"((A)[2]), "r"((A)[3]), "r"((B)[0]), "r"((B)[1]))

// ---------------------------------------------------------------------------
// gap: one block per (b,c) row of 16384 pixels
// ---------------------------------------------------------------------------
__global__ void gap_kernel(const float* __restrict__ x) {
    const int bc = blockIdx.x;
    const float4* p = (const float4*)(x + (size_t)bc * NPIX);
    float s = 0.f;
    for (int i = threadIdx.x; i < NPIX / 4; i += 256) {
        float4 v = p[i];
        s += (v.x + v.y) + (v.z + v.w);
    }
    #pragma unroll
    for (int o = 16; o; o >>= 1) s += __shfl_down_sync(0xffffffffu, s, o);
    __shared__ float red[8];
    if ((threadIdx.x & 31) == 0) red[threadIdx.x >> 5] = s;
    __syncthreads();
    if (threadIdx.x == 0) {
        float tot = 0.f;
        #pragma unroll
        for (int i = 0; i < 8; i++) tot += red[i];
        g_gap[bc] = tot * (1.f / NPIX);
    }
}

// ---------------------------------------------------------------------------
// gate: softmax -> top2 -> gated weights + aux loss
// ---------------------------------------------------------------------------
__global__ void gate_kernel(const float* __restrict__ gw,
                            const float* __restrict__ gb,
                            float* __restrict__ aux_out) {
    __shared__ float logit_s[BATCH][EE];
    __shared__ float gsh[BATCH][EE];
    const int t = threadIdx.x;
    if (t < BATCH * EE) {
        const int b = t >> 2, e = t & 3;
        float s = gb[e];
        const float* gp = g_gap + b * CC;
        #pragma unroll 8
        for (int c = 0; c < CC; c++) s += gp[c] * gw[e * CC + c];
        logit_s[b][e] = s;
    }
    __syncthreads();
    if (t < BATCH) {
        const int b = t;
        float l[EE];
        float mx = -1e30f;
        #pragma unroll
        for (int e = 0; e < EE; e++) { l[e] = logit_s[b][e]; mx = fmaxf(mx, l[e]); }
        float sum = 0.f;
        #pragma unroll
        for (int e = 0; e < EE; e++) { l[e] = expf(l[e] - mx); sum += l[e]; }
        #pragma unroll
        for (int e = 0; e < EE; e++) l[e] /= sum;
        int i1 = 0;
        for (int e = 1; e < EE; e++) if (l[e] > l[i1]) i1 = e;
        int i2 = -1;
        for (int e = 0; e < EE; e++) {
            if (e == i1) continue;
            if (i2 < 0 || l[e] > l[i2]) i2 = e;
        }
        const float denom = l[i1] + l[i2] + 1e-8f;
        #pragma unroll
        for (int e = 0; e < EE; e++) {
            float gv = (e == i1 || e == i2) ? l[e] / denom : 0.f;
            gsh[b][e] = gv;
            g_gated[b * EE + e] = gv;
        }
    }
    __syncthreads();
    if (t == 0) {
        float u[EE];
        float mean = 0.f;
        #pragma unroll
        for (int e = 0; e < EE; e++) {
            float s = 0.f;
            for (int b = 0; b < BATCH; b++) s += gsh[b][e];
            u[e] = s;
            mean += s;
        }
        mean *= (1.f / EE);
        float var = 0.f;
        #pragma unroll
        for (int e = 0; e < EE; e++) { float d = u[e] - mean; var += d * d; }
        var *= (1.f / EE);
        *aux_out = var / (mean * mean + 1e-10f);
    }
}

// ---------------------------------------------------------------------------
// prep: BN-fold weights, split hi/lo bf16 into device arrays (unpadded)
// ---------------------------------------------------------------------------
__global__ void prep_kernel(const float* __restrict__ W1, const float* __restrict__ b1,
                            const float* __restrict__ g1, const float* __restrict__ be1,
                            const float* __restrict__ m1, const float* __restrict__ v1,
                            const float* __restrict__ W2, const float* __restrict__ b2,
                            const float* __restrict__ g2, const float* __restrict__ be2,
                            const float* __restrict__ m2, const float* __restrict__ v2,
                            const float* __restrict__ W3) {
    const int e = blockIdx.x, t = threadIdx.x;
    __shared__ float i1[HID], i2[HID];
    if (t < HID) {
        float a = g1[e * HID + t] * rsqrtf(v1[e * HID + t] + 1e-5f);
        i1[t] = a;
        g_t1[e * HID + t] = (b1[e * HID + t] - m1[e * HID + t]) * a + be1[e * HID + t];
        float c = g2[e * HID + t] * rsqrtf(v2[e * HID + t] + 1e-5f);
        i2[t] = c;
        g_t2[e * HID + t] = (b2[e * HID + t] - m2[e * HID + t]) * c + be2[e * HID + t];
    }
    __syncthreads();
    for (int idx = t; idx < HID * CC; idx += 256) {           // W1 [o][i]
        int o = idx >> 6;
        unsigned short h, l;
        split1(W1[(size_t)e * HID * CC + idx] * i1[o], h, l);
        g_w1h[e * 8192 + idx] = h;
        g_w1l[e * 8192 + idx] = l;
    }
    for (int idx = t; idx < HID * HID; idx += 256) {          // W2 [o][i]
        int o = idx >> 7;
        unsigned short h, l;
        split1(W2[(size_t)e * HID * HID + idx] * i2[o], h, l);
        g_w2h[e * 16384 + idx] = h;
        g_w2l[e * 16384 + idx] = l;
    }
    for (int idx = t; idx < CC * HID; idx += 256) {           // W3 [c][i], no fold
        unsigned short h, l;
        split1(W3[(size_t)e * CC * HID + idx], h, l);
        g_w3h[e * 8192 + idx] = h;
        g_w3l[e * 8192 + idx] = l;
    }
}

// ---------------------------------------------------------------------------
// act-GEMM (layers 1/2): D = A(act [px][K]) @ B(W [N][K])^T; bias+relu;
// split -> dst [px][N] hi/lo.  warps: mg=w&1 (32 px), ng=w>>1 (32 out chans)
// ---------------------------------------------------------------------------
__device__ __forceinline__ void gemm_act(
    unsigned char* smraw, uint32_t sb,
    uint32_t aH, uint32_t aL, uint32_t bH, uint32_t bL,
    int strideA, int strideB, int KT,
    uint32_t dstH, uint32_t dstL, const float* biasS,
    int lane, int mg, int ng)
{
    float d[8][4];
    #pragma unroll
    for (int i = 0; i < 8; i++)
        #pragma unroll
        for (int j = 0; j < 4; j++) d[i][j] = 0.f;

    const int rowA = mg * 32 + (lane & 15);
    const int colA = (lane >> 4) * 8;
    const int rowB = ng * 32 + (lane & 7);
    const int colB = ((lane >> 3) & 1) * 8;

    #pragma unroll
    for (int pass = 0; pass < 3; pass++) {
        const uint32_t aB = (pass == 1) ? aL : aH;
        const uint32_t bB = (pass == 2) ? bL : bH;
        for (int k = 0; k < KT; k++) {
            uint32_t a0[4], a1[4];
            LDSM4(a0, aB + (uint32_t)(rowA * strideA + k * 16 + colA) * 2);
            LDSM4(a1, aB + (uint32_t)((rowA + 16) * strideA + k * 16 + colA) * 2);
            #pragma unroll
            for (int nt = 0; nt < 4; nt++) {
                uint32_t bb[2];
                LDSM2(bb, bB + (uint32_t)((rowB + nt * 8) * strideB + k * 16 + colB) * 2);
                MMA(d[nt], a0, bb);
                MMA(d[4 + nt], a1, bb);
            }
        }
    }

    const int rbase = mg * 32 + (lane >> 2);
    #pragma unroll
    for (int mt = 0; mt < 2; mt++) {
        const int r = rbase + mt * 16;
        #pragma unroll
        for (int nt = 0; nt < 4; nt++) {
            const int n = ng * 32 + nt * 8 + (lane & 3) * 2;
            const float bx = biasS[n], by = biasS[n + 1];
            const float* dd = d[mt * 4 + nt];
            uint32_t h, l;
            split2(fmaxf(dd[0] + bx, 0.f), fmaxf(dd[1] + by, 0.f), h, l);
            *(uint32_t*)(smraw + dstH + (r * SD128 + n) * 2) = h;
            *(uint32_t*)(smraw + dstL + (r * SD128 + n) * 2) = l;
            split2(fmaxf(dd[2] + bx, 0.f), fmaxf(dd[3] + by, 0.f), h, l);
            *(uint32_t*)(smraw + dstH + ((r + 8) * SD128 + n) * 2) = h;
            *(uint32_t*)(smraw + dstL + ((r + 8) * SD128 + n) * 2) = l;
        }
    }
}

// ---------------------------------------------------------------------------
// main fused MMA kernel: one CTA per (chunk, expert, batch)
// ---------------------------------------------------------------------------
__global__ __launch_bounds__(TPB, 1)
void moe_mma(const float* __restrict__ x, const float* __restrict__ b3,
             float* __restrict__ out) {
    extern __shared__ unsigned char smraw[];
    const int chunk = blockIdx.x, e = blockIdx.y, b = blockIdx.z;
    const float gval = g_gated[b * EE + e];
    if (gval == 0.f) return;

    const uint32_t sb = smem_u32(smraw);
    const int tid = threadIdx.x, w = tid >> 5, lane = tid & 31;

    // ---- copy prepped weights into padded SMEM ----
    {
        const int4* s1h = (const int4*)(g_w1h + e * 8192);
        const int4* s1l = (const int4*)(g_w1l + e * 8192);
        for (int j = tid; j < 1024; j += TPB) {
            int o = j >> 3, cb = (j & 7) * 16;
            *(int4*)(smraw + S_W1H + o * 144 + cb) = s1h[j];
            *(int4*)(smraw + S_W1L + o * 144 + cb) = s1l[j];
        }
        const int4* s2h = (const int4*)(g_w2h + e * 16384);
        const int4* s2l = (const int4*)(g_w2l + e * 16384);
        for (int j = tid; j < 2048; j += TPB) {
            int o = j >> 4, cb = (j & 15) * 16;
            *(int4*)(smraw + S_W2H + o * 272 + cb) = s2h[j];
            *(int4*)(smraw + S_W2L + o * 272 + cb) = s2l[j];
        }
        const int4* s3h = (const int4*)(g_w3h + e * 8192);
        const int4* s3l = (const int4*)(g_w3l + e * 8192);
        for (int j = tid; j < 1024; j += TPB) {
            int o = j >> 4, cb = (j & 15) * 16;
            *(int4*)(smraw + S_W3H + o * 272 + cb) = s3h[j];
            *(int4*)(smraw + S_W3L + o * 272 + cb) = s3l[j];
        }
        float* t1p = (float*)(smraw + S_T1);
        float* t2p = (float*)(smraw + S_T2);
        float* b3p = (float*)(smraw + S_B3);
        for (int i = tid; i < HID; i += TPB) {
            t1p[i] = g_t1[e * HID + i];
            t2p[i] = g_t2[e * HID + i];
        }
        for (int i = tid; i < CC; i += TPB) b3p[i] = b3[e * CC + i];
    }

    const float* xb = x + (size_t)b * CC * NPIX;
    float* ob = out + (size_t)b * CC * NPIX;
    const float* t1s = (const float*)(smraw + S_T1);
    const float* t2s = (const float*)(smraw + S_T2);
    const float* b3s = (const float*)(smraw + S_B3);
    const int mg = w & 1, ng = w >> 1;

    for (int tl = 0; tl < TILES_PER_CTA; ++tl) {
        const int pg0 = chunk * (TILES_PER_CTA * TILE_PX) + tl * TILE_PX;

        __syncthreads();   // previous tile's layer-3 reads of H2/X region done

        // ---- load X tile (64c x 64px), split, store [px][chan] hi/lo ----
        {
            const int c0 = (tid & 31) * 2, pb = tid >> 5;   // 8 px per thread
            const float* r0 = xb + (size_t)c0 * NPIX + pg0 + pb * 8;
            const float* r1 = r0 + NPIX;
            float4 a0 = *(const float4*)(r0);
            float4 a1 = *(const float4*)(r0 + 4);
            float4 q0 = *(const float4*)(r1);
            float4 q1 = *(const float4*)(r1 + 4);
            const float va[8] = {a0.x, a0.y, a0.z, a0.w, a1.x, a1.y, a1.z, a1.w};
            const float vb[8] = {q0.x, q0.y, q0.z, q0.w, q1.x, q1.y, q1.z, q1.w};
            #pragma unroll
            for (int j = 0; j < 8; j++) {
                uint32_t h, l;
                split2(va[j], vb[j], h, l);     // (chan c0, c0+1) pair
                const int off = ((pb * 8 + j) * SD64 + c0) * 2;
                *(uint32_t*)(smraw + S_H2H + off) = h;
                *(uint32_t*)(smraw + S_H2L + off) = l;
            }
        }
        __syncthreads();

        // ---- layer 1: H1 = relu(X @ W1^T + t1) ----
        gemm_act(smraw, sb, sb + S_H2H, sb + S_H2L, sb + S_W1H, sb + S_W1L,
                 SD64, SD64, 4, S_H1H, S_H1L, t1s, lane, mg, ng);
        __syncthreads();

        // ---- layer 2: H2 = relu(H1 @ W2^T + t2) ----
        gemm_act(smraw, sb, sb + S_H1H, sb + S_H1L, sb + S_W2H, sb + S_W2L,
                 SD128, SD128, 8, S_H2H, S_H2L, t2s, lane, mg, ng);
        __syncthreads();

        // ---- layer 3: out += gval*(W3 @ H2 + b3) ----
        {
            float d[4][4];
            #pragma unroll
            for (int i = 0; i < 4; i++)
                #pragma unroll
                for (int j = 0; j < 4; j++) d[i][j] = 0.f;

            const int m0 = (w & 1) * 32;          // chan base (2 m-tiles)
            const int n0 = (w >> 1) * 16;         // px base (2 n-tiles)
            const int rowA = m0 + (lane & 15);
            const int colA = (lane >> 4) * 8;
            const int rowB = n0 + (lane & 7);
            const int colB = ((lane >> 3) & 1) * 8;

            #pragma unroll
            for (int pass = 0; pass < 3; pass++) {
                const uint32_t aB = sb + ((pass == 1) ? S_W3L : S_W3H);
                const uint32_t bB = sb + ((pass == 2) ? S_H2L : S_H2H);
                for (int k = 0; k < 8; k++) {
                    uint32_t a0[4], a1[4];
                    LDSM4(a0, aB + (uint32_t)(rowA * SD128 + k * 16 + colA) * 2);
                    LDSM4(a1, aB + (uint32_t)((rowA + 16) * SD128 + k * 16 + colA) * 2);
                    #pragma unroll
                    for (int nt = 0; nt < 2; nt++) {
                        uint32_t bb[2];
                        LDSM2(bb, bB + (uint32_t)((rowB + nt * 8) * SD128 + k * 16 + colB) * 2);
                        MMA(d[nt], a0, bb);
                        MMA(d[2 + nt], a1, bb);
                    }
                }
            }
            const int rb = m0 + (lane >> 2);
            #pragma unroll
            for (int mt = 0; mt < 2; mt++) {
                const int r = rb + mt * 16;
                const float bz0 = b3s[r], bz1 = b3s[r + 8];
                #pragma unroll
                for (int nt = 0; nt < 2; nt++) {
                    const int c = n0 + nt * 8 + (lane & 3) * 2;
                    const float* dd = d[mt * 2 + nt];
                    float f0 = (dd[0] + bz0) * gval, f1 = (dd[1] + bz0) * gval;
                    float f2 = (dd[2] + bz1) * gval, f3 = (dd[3] + bz1) * gval;
                    float* p0 = ob + (size_t)r * NPIX + pg0 + c;
                    float* p1 = ob + (size_t)(r + 8) * NPIX + pg0 + c;
                    asm volatile("red.global.add.v2.f32 [%0], {%1,%2};"
                                 :: "l"(p0), "f"(f0), "f"(f1) : "memory");
                    asm volatile("red.global.add.v2.f32 [%0], {%1,%2};"
                                 :: "l"(p1), "f"(f2), "f"(f3) : "memory");
                }
            }
        }
    }
}

// ---------------------------------------------------------------------------
extern "C" void kernel_launch(void* const* d_in, const int* in_sizes, int n_in,
                              void* d_out, int out_size) {
    const float* x   = (const float*)d_in[0];
    const float* W1  = (const float*)d_in[1];
    const float* b1  = (const float*)d_in[2];
    const float* g1  = (const float*)d_in[3];
    const float* be1 = (const float*)d_in[4];
    const float* m1  = (const float*)d_in[5];
    const float* v1  = (const float*)d_in[6];
    const float* W2  = (const float*)d_in[7];
    const float* b2  = (const float*)d_in[8];
    const float* g2  = (const float*)d_in[9];
    const float* be2 = (const float*)d_in[10];
    const float* m2  = (const float*)d_in[11];
    const float* v2  = (const float*)d_in[12];
    const float* W3  = (const float*)d_in[13];
    const float* b3  = (const float*)d_in[14];
    const float* gw  = (const float*)d_in[15];
    const float* gb  = (const float*)d_in[16];
    float* out = (float*)d_out;

    cudaMemsetAsync(out, 0, (size_t)(out_size - 1) * sizeof(float), 0);
    gap_kernel<<<BATCH * CC, 256>>>(x);
    gate_kernel<<<1, 64>>>(gw, gb, out + (out_size - 1));
    prep_kernel<<<EE, 256>>>(W1, b1, g1, be1, m1, v1,
                             W2, b2, g2, be2, m2, v2, W3);

    cudaFuncSetAttribute(moe_mma, cudaFuncAttributeMaxDynamicSharedMemorySize,
                         SMEM_BYTES);
    dim3 grid(NCHUNK, EE, BATCH);
    moe_mma<<<grid, TPB, SMEM_BYTES>>>(x, b3, out);
}